// round 10
// baseline (speedup 1.0000x reference)
#include <cuda_runtime.h>
#include <cstdint>

// Problem constants
#define BATCH 64
#define TSTEPS 2048
#define DIN 128
#define HID 256
#define DOUT 128
#define G4H (4*HID)        // 1024

#define NTHREADS 256
#define KC 32              // K per warp (8 warps)
#define BPC 8

// ---- NEW scan: 32 cg x 8 bg = 256 CTAs, 2 per SM
#define N_NCTA 256
#define N_NCG 32
#define N_JPC 8            // hidden units per CTA
#define N_NCOL 32          // gate cols per CTA
#define N_SWSTR 34
#define N_HSTR 12          // floats per sH row (48B, 16B-aligned)
#define N_PSTR 10
#define N_SW2   0
#define N_H     (N_SW2 + 256*N_SWSTR)       // 8704
#define N_PART  (N_H + 256*N_HSTR)          // +3072
#define N_C     (N_PART + 2*256*N_PSTR)     // +5120
#define N_FLOATS (N_C + 64)
#define N_SMEM_BYTES (N_FLOATS*4)           // 67,840 B

// ---- FALLBACK scan (R9): 16 cg x 8 bg = 128 CTAs
#define F_NCTA 128
#define F_JPC 16
#define F_NCOL 64
#define F_SWSTR 66
#define F_PSTR 70
#define F_SW2   0
#define F_H     (F_SW2 + 256*F_SWSTR)
#define F_PART  (F_H + 256*8)
#define F_C     (F_PART + 2*8*8*F_PSTR)
#define F_FLOATS (F_C + 128)
#define F_SMEM_BYTES (F_FLOATS*4)

// x_proj kernel smem
#define XP_XSTRIDE 133
#define XP_WSTRIDE 132
#define XPK_SX    0
#define XPK_SW    (128*XP_XSTRIDE)
#define XPK_FLOATS (XPK_SW + 128*XP_WSTRIDE)
#define XPK_BYTES (XPK_FLOATS*4)

// Global scratch (shared by both scan variants)
// g_xp[t][cg32][bg][bb*32 + gate*8 + lj]
__device__ __align__(16) float g_xp[(size_t)TSTEPS * N_NCG * 8 * 256];
// tagged h words {hi32=tag, lo32=h}: [buf][bg][cg32][lj8*8+bb]
__device__ __align__(16) unsigned long long g_hx[2][8][N_NCG][64];

__device__ __forceinline__ uint32_t smem_u32(const void* p) {
    return (uint32_t)__cvta_generic_to_shared(p);
}
__device__ __forceinline__ float fast_sig(float x) {
    return __fdividef(1.0f, 1.0f + __expf(-x));
}
__device__ __forceinline__ float fast_tanh(float x) {
    return __fdividef(2.0f, 1.0f + __expf(-2.0f * x)) - 1.0f;
}
__device__ __forceinline__ unsigned long long ld_relaxed_u64(
        const unsigned long long* p) {
    unsigned long long v;
    asm volatile("ld.relaxed.gpu.global.u64 %0, [%1];"
                 : "=l"(v) : "l"(p) : "memory");
    return v;
}
__device__ __forceinline__ void st_relaxed_u64(unsigned long long* p,
                                               unsigned long long v) {
    asm volatile("st.relaxed.gpu.global.u64 [%0], %1;"
                 :: "l"(p), "l"(v) : "memory");
}

// ---------------------------------------------------------------------------
__global__ void init_kernel() {
    int i = blockIdx.x * blockDim.x + threadIdx.x;
    if (i < 2 * 8 * N_NCG * 64) ((unsigned long long*)g_hx)[i] = 0ull;
}

// ---------------------------------------------------------------------------
// x_proj: g_xp[t][cg][bg][bb*32 + gate*8+lj] = x[b,t,:] . W_x[:, gcol] + bias
// ---------------------------------------------------------------------------
__global__ void __launch_bounds__(NTHREADS, 1)
xproj_kernel(const float* __restrict__ x,
             const float* __restrict__ W_x,
             const float* __restrict__ bias) {
    extern __shared__ float smem[];
    float* sX = smem + XPK_SX;
    float* sW = smem + XPK_SW;

    const int tid  = threadIdx.x;
    const int tblk = blockIdx.x;
    const int bg   = blockIdx.y;

    for (int idx = tid; idx < 128 * 32; idx += NTHREADS) {
        int r = idx >> 5, f4 = idx & 31;
        int tt = r >> 3, bb = r & 7;
        int b = bg * 8 + bb, t = tblk * 16 + tt;
        float4 v = __ldg(reinterpret_cast<const float4*>(
            x + ((size_t)b * TSTEPS + t) * DIN) + f4);
        float* dst = sX + r * XP_XSTRIDE + f4 * 4;
        dst[0] = v.x; dst[1] = v.y; dst[2] = v.z; dst[3] = v.w;
    }

    const int cq = tid & 7;
    const int rg = tid >> 3;

    for (int p = 0; p < 8; p++) {
        const int cp0 = p * 128;
        __syncthreads();
        for (int idx = tid; idx < 128 * 32; idx += NTHREADS) {
            int d = idx >> 5, c4 = idx & 31;
            float4 v = __ldg(reinterpret_cast<const float4*>(
                W_x + (size_t)d * G4H + cp0) + c4);
            float* dst = sW + d * XP_WSTRIDE + c4 * 4;
            dst[0] = v.x; dst[1] = v.y; dst[2] = v.z; dst[3] = v.w;
        }
        __syncthreads();

        unsigned long long acc[4][8];
        #pragma unroll
        for (int qq = 0; qq < 8; qq++) {
            float2 bv = __ldg(reinterpret_cast<const float2*>(
                bias + cp0 + 2 * (cq + 8 * qq)));
            unsigned long long bu;
            asm("mov.b64 %0, {%1, %2};" : "=l"(bu) : "f"(bv.x), "f"(bv.y));
            #pragma unroll
            for (int rr = 0; rr < 4; rr++) acc[rr][qq] = bu;
        }

        #pragma unroll 4
        for (int d = 0; d < 128; d++) {
            unsigned long long x2[4];
            #pragma unroll
            for (int rr = 0; rr < 4; rr++) {
                float xv = sX[(rg * 4 + rr) * XP_XSTRIDE + d];
                asm("mov.b64 %0, {%1, %1};" : "=l"(x2[rr]) : "f"(xv));
            }
            const uint32_t wrow = smem_u32(sW + d * XP_WSTRIDE + 2 * cq);
            #pragma unroll
            for (int qq = 0; qq < 8; qq++) {
                unsigned long long w2;
                asm volatile("ld.shared.u64 %0, [%1];"
                             : "=l"(w2) : "r"(wrow + qq * 64));
                #pragma unroll
                for (int rr = 0; rr < 4; rr++)
                    asm volatile("fma.rn.f32x2 %0, %1, %2, %0;"
                                 : "+l"(acc[rr][qq]) : "l"(x2[rr]), "l"(w2));
            }
        }

        #pragma unroll
        for (int rr = 0; rr < 4; rr++) {
            int r = rg * 4 + rr;
            int tt = r >> 3, bb = r & 7;
            int t = tblk * 16 + tt;
            #pragma unroll
            for (int qq = 0; qq < 8; qq++) {
                int cglob = cp0 + 2 * (cq + 8 * qq);
                int gate = cglob >> 8, j = cglob & 255;
                int cg = j >> 3, lj = j & 7;
                float lo, hi;
                asm("mov.b64 {%0,%1}, %2;" : "=f"(lo), "=f"(hi) : "l"(acc[rr][qq]));
                float2* dst = reinterpret_cast<float2*>(
                    g_xp + ((size_t)((t * N_NCG + cg) * 8 + bg)) * 256
                         + bb * 32 + gate * 8 + lj);
                *dst = make_float2(lo, hi);
            }
        }
    }
}

// ---------------------------------------------------------------------------
// NEW scan: 256 CTAs, 2/SM. Thread = 1 gate column; W pre-splatted in regs.
// ---------------------------------------------------------------------------
__global__ void __launch_bounds__(NTHREADS, 2)
lstm_scan2(const float* __restrict__ W_h) {
    extern __shared__ float smem[];
    float* sW2   = smem + N_SW2;    // [k][c] staging (setup only)
    float* sH    = smem + N_H;      // [k][12]  rows of 8 h + pad
    float* sPart = smem + N_PART;   // [buf][w*32+c][10]
    float* sC    = smem + N_C;      // [lj*8+bb], 64

    const int tid = threadIdx.x;
    const int cg  = blockIdx.x & (N_NCG - 1);
    const int bg  = blockIdx.x >> 5;
    const int j0  = cg * N_JPC;

    // stage W_h slice [k][c], c = gate*8+lj
    for (int idx = tid; idx < 256 * N_NCOL; idx += NTHREADS) {
        int k = idx >> 5, c = idx & 31;
        int gate = c >> 3, lj = c & 7;
        sW2[k * N_SWSTR + c] = W_h[(size_t)k * G4H + gate * HID + j0 + lj];
    }
    if (tid < 64) sC[tid] = 0.0f;
    __syncthreads();

    const int w    = tid >> 5;       // warp = k-chunk
    const int lane = tid & 31;       // lane = my gate column

    // pre-splatted W: wsplat[k] = {W[c][k0+k], same}
    unsigned long long wsplat[KC];
    #pragma unroll
    for (int k = 0; k < KC; k++) {
        float wv = sW2[(32 * w + k) * N_SWSTR + lane];
        asm("mov.b64 %0, {%1, %1};" : "=l"(wsplat[k]) : "f"(wv));
    }

    const unsigned long long* hx_flat = (const unsigned long long*)g_hx;
    const size_t base_lane =
        ((size_t)bg * N_NCG + (4 * w + (lane >> 3))) * 64 + (lane & 7) * 8;

    const uint32_t hrow  = smem_u32(sH) + (32 * w + lane) * (N_HSTR * 4);
    const uint32_t hgemm = smem_u32(sH) + (32 * w) * (N_HSTR * 4);

    const int lj = tid >> 3;         // epilogue decode (tid<64)
    const int bb = tid & 7;

    for (int s = 0; s < TSTEPS; s++) {
        const int rbuf = s & 1;

        // ---- prefetch x_proj gate inputs (tid<64)
        float xr[4];
        if (tid < 64) {
            const float* xpb = g_xp
                + ((size_t)((s * N_NCG + cg) * 8 + bg)) * 256 + bb * 32 + lj;
            #pragma unroll
            for (int g = 0; g < 4; g++) xr[g] = __ldg(xpb + g * 8);
        }

        // ---- poll tagged words (predicated reload of only-stale words)
        const unsigned long long* ps = hx_flat + (size_t)rbuf * (8 * N_NCG * 64)
                                     + base_lane;
        unsigned long long v[8];
        const unsigned exp_tag = (unsigned)s;
        #pragma unroll
        for (int i = 0; i < 8; i++) v[i] = ld_relaxed_u64(ps + i);
        for (;;) {
            bool all_ok = true;
            #pragma unroll
            for (int i = 0; i < 8; i++) {
                if ((unsigned)(v[i] >> 32) != exp_tag) {
                    v[i] = ld_relaxed_u64(ps + i);
                    all_ok = false;
                }
            }
            if (__all_sync(0xffffffffu, all_ok)) break;
        }
        // ---- stage my h row (k = 32w + lane), batches 0..7
        asm volatile("st.shared.v4.f32 [%0], {%1,%2,%3,%4};"
                     :: "r"(hrow),
                        "f"(__uint_as_float((unsigned)v[0])),
                        "f"(__uint_as_float((unsigned)v[1])),
                        "f"(__uint_as_float((unsigned)v[2])),
                        "f"(__uint_as_float((unsigned)v[3])));
        asm volatile("st.shared.v4.f32 [%0], {%1,%2,%3,%4};"
                     :: "r"(hrow + 16),
                        "f"(__uint_as_float((unsigned)v[4])),
                        "f"(__uint_as_float((unsigned)v[5])),
                        "f"(__uint_as_float((unsigned)v[6])),
                        "f"(__uint_as_float((unsigned)v[7])));
        __syncwarp();

        // ---- GEMM: per k: 2 broadcast LDS (4 batch-pairs) + 4 FMA2, no movs
        unsigned long long a0 = 0ull, a1 = 0ull, a2 = 0ull, a3 = 0ull;
        #pragma unroll
        for (int k = 0; k < KC; k++) {
            unsigned long long p01, p23, p45, p67;
            asm volatile("ld.shared.v2.u64 {%0,%1}, [%2];"
                         : "=l"(p01), "=l"(p23) : "r"(hgemm + k * 48));
            asm volatile("ld.shared.v2.u64 {%0,%1}, [%2];"
                         : "=l"(p45), "=l"(p67) : "r"(hgemm + k * 48 + 16));
            asm volatile("fma.rn.f32x2 %0, %1, %2, %0;"
                         : "+l"(a0) : "l"(p01), "l"(wsplat[k]));
            asm volatile("fma.rn.f32x2 %0, %1, %2, %0;"
                         : "+l"(a1) : "l"(p23), "l"(wsplat[k]));
            asm volatile("fma.rn.f32x2 %0, %1, %2, %0;"
                         : "+l"(a2) : "l"(p45), "l"(wsplat[k]));
            asm volatile("fma.rn.f32x2 %0, %1, %2, %0;"
                         : "+l"(a3) : "l"(p67), "l"(wsplat[k]));
        }

        // ---- partials: [w*32+c][b] stride 10
        {
            float* sP = sPart + rbuf * (256 * N_PSTR);
            const uint32_t pa = smem_u32(sP + (w * 32 + lane) * N_PSTR);
            asm volatile("st.shared.u64 [%0], %1;"      :: "r"(pa),      "l"(a0));
            asm volatile("st.shared.u64 [%0], %1;"      :: "r"(pa + 8),  "l"(a1));
            asm volatile("st.shared.u64 [%0], %1;"      :: "r"(pa + 16), "l"(a2));
            asm volatile("st.shared.u64 [%0], %1;"      :: "r"(pa + 24), "l"(a3));
        }
        __syncthreads();

        // ---- epilogue (tid<64): reduce 8 k-chunks, activations, publish
        if (tid < 64) {
            const float* sP = sPart + rbuf * (256 * N_PSTR);
            float g4[4];
            #pragma unroll
            for (int g = 0; g < 4; g++) {
                float vv = xr[g];
                #pragma unroll
                for (int q = 0; q < 8; q++)
                    vv += sP[(q * 32 + g * 8 + lj) * N_PSTR + bb];
                g4[g] = vv;
            }
            float ig = fast_sig(g4[0]);
            float fg = fast_sig(g4[1]);
            float gg = fast_tanh(g4[2]);
            float og = fast_sig(g4[3]);
            float cnew = fg * sC[tid] + ig * gg;
            sC[tid] = cnew;
            float hnew = og * fast_tanh(cnew);

            unsigned long long pk;
            asm("mov.b64 %0, {%1, %2};"
                : "=l"(pk) : "r"(__float_as_uint(hnew)), "r"((unsigned)(s + 1)));
            st_relaxed_u64(&g_hx[rbuf ^ 1][bg][cg][tid], pk);
        }
    }
}

// ---------------------------------------------------------------------------
// FALLBACK scan (R9 layout, 128 CTAs) — used only if 2/SM occupancy fails
// ---------------------------------------------------------------------------
__global__ void __launch_bounds__(NTHREADS, 1)
lstm_scan_fb(const float* __restrict__ W_h) {
    extern __shared__ float smem[];
    float* sW2   = smem + F_SW2;
    float* sH    = smem + F_H;
    float* sPart = smem + F_PART;
    float* sC    = smem + F_C;

    const int tid = threadIdx.x;
    const int cg  = blockIdx.x & 15;
    const int bg  = blockIdx.x >> 4;
    const int j0  = cg * F_JPC;

    for (int idx = tid; idx < 256 * F_NCOL; idx += NTHREADS) {
        int k = idx >> 6, c = idx & 63;
        int gate = c >> 4, lj = c & 15;
        sW2[k * F_SWSTR + c] = W_h[(size_t)k * G4H + gate * HID + j0 + lj];
    }
    if (tid < 128) sC[tid] = 0.0f;
    __syncthreads();

    const int w    = tid >> 5;
    const int lane = tid & 31;
    const int hw   = lane >> 4;
    const int lc   = lane & 15;
    const int k0   = w * KC;
    const int c0   = 4 * lc;

    unsigned long long wreg[2][KC];
    {
        const uint32_t wb = smem_u32(sW2 + k0 * F_SWSTR + c0);
        #pragma unroll
        for (int k = 0; k < KC; k++) {
            asm volatile("ld.shared.u64 %0, [%1];"
                         : "=l"(wreg[0][k]) : "r"(wb + k * (F_SWSTR * 4)));
            asm volatile("ld.shared.u64 %0, [%1];"
                         : "=l"(wreg[1][k]) : "r"(wb + k * (F_SWSTR * 4) + 8));
        }
    }
    __syncthreads();

    const uint32_t hbase  = smem_u32(sH + k0 * BPC + 4 * hw);
    const uint32_t hstore = smem_u32(sH + k0 * BPC) + lane * 16;

    const int lj = tid >> 3;
    const int bb = tid & 7;

    for (int s = 0; s < TSTEPS; s++) {
        const int rbuf = s & 1;
        float* sP = sPart + rbuf * (8 * BPC * F_PSTR);

        float xr[4];
        if (tid < 128) {
            int cg32 = cg * 2 + (lj >> 3);
            const float* xpb = g_xp
                + ((size_t)((s * N_NCG + cg32) * 8 + bg)) * 256
                + bb * 32 + (lj & 7);
            #pragma unroll
            for (int g = 0; g < 4; g++) xr[g] = __ldg(xpb + g * 8);
        }

        const unsigned long long* pA = &g_hx[rbuf][bg][4 * w][0] + 4 * lane;
        const unsigned long long* pB = &g_hx[rbuf][bg][4 * w + 2][0] + 4 * lane;
        unsigned long long va[4], vb[4];
        const unsigned exp_tag = (unsigned)s;
        #pragma unroll
        for (int i = 0; i < 4; i++) { va[i] = ld_relaxed_u64(pA + i);
                                      vb[i] = ld_relaxed_u64(pB + i); }
        for (;;) {
            bool all_ok = true;
            #pragma unroll
            for (int i = 0; i < 4; i++) {
                if ((unsigned)(va[i] >> 32) != exp_tag) {
                    va[i] = ld_relaxed_u64(pA + i); all_ok = false;
                }
                if ((unsigned)(vb[i] >> 32) != exp_tag) {
                    vb[i] = ld_relaxed_u64(pB + i); all_ok = false;
                }
            }
            if (__all_sync(0xffffffffu, all_ok)) break;
        }
        asm volatile("st.shared.v4.f32 [%0], {%1,%2,%3,%4};"
                     :: "r"(hstore),
                        "f"(__uint_as_float((unsigned)va[0])),
                        "f"(__uint_as_float((unsigned)va[1])),
                        "f"(__uint_as_float((unsigned)va[2])),
                        "f"(__uint_as_float((unsigned)va[3])));
        asm volatile("st.shared.v4.f32 [%0], {%1,%2,%3,%4};"
                     :: "r"(hstore + 512),
                        "f"(__uint_as_float((unsigned)vb[0])),
                        "f"(__uint_as_float((unsigned)vb[1])),
                        "f"(__uint_as_float((unsigned)vb[2])),
                        "f"(__uint_as_float((unsigned)vb[3])));
        __syncwarp();

        unsigned long long acc[2][4];
        #pragma unroll
        for (int p = 0; p < 2; p++)
            #pragma unroll
            for (int i = 0; i < 4; i++) acc[p][i] = 0ull;

        #pragma unroll
        for (int k = 0; k < KC; k++) {
            float h0, h1, h2f, h3;
            asm volatile("ld.shared.v4.f32 {%0,%1,%2,%3}, [%4];"
                         : "=f"(h0), "=f"(h1), "=f"(h2f), "=f"(h3)
                         : "r"(hbase + k * 32));
            unsigned long long hh[4];
            asm("mov.b64 %0, {%1, %1};" : "=l"(hh[0]) : "f"(h0));
            asm("mov.b64 %0, {%1, %1};" : "=l"(hh[1]) : "f"(h1));
            asm("mov.b64 %0, {%1, %1};" : "=l"(hh[2]) : "f"(h2f));
            asm("mov.b64 %0, {%1, %1};" : "=l"(hh[3]) : "f"(h3));
            #pragma unroll
            for (int i = 0; i < 4; i++) {
                asm volatile("fma.rn.f32x2 %0, %1, %2, %0;"
                             : "+l"(acc[0][i]) : "l"(hh[i]), "l"(wreg[0][k]));
                asm volatile("fma.rn.f32x2 %0, %1, %2, %0;"
                             : "+l"(acc[1][i]) : "l"(hh[i]), "l"(wreg[1][k]));
            }
        }

        #pragma unroll
        for (int i = 0; i < 4; i++) {
            int row = (w * BPC + 4 * hw + i) * F_PSTR;
            *reinterpret_cast<unsigned long long*>(sP + row + c0)     = acc[0][i];
            *reinterpret_cast<unsigned long long*>(sP + row + c0 + 2) = acc[1][i];
        }
        __syncthreads();

        if (tid < 128) {
            float g4[4];
            #pragma unroll
            for (int g = 0; g < 4; g++) {
                int c = g * F_JPC + lj;
                float vv = xr[g];
                #pragma unroll
                for (int q = 0; q < 8; q++)
                    vv += sP[(q * BPC + bb) * F_PSTR + c];
                g4[g] = vv;
            }
            float ig = fast_sig(g4[0]);
            float fg = fast_sig(g4[1]);
            float gg = fast_tanh(g4[2]);
            float og = fast_sig(g4[3]);
            float cnew = fg * sC[tid] + ig * gg;
            sC[tid] = cnew;
            float hnew = og * fast_tanh(cnew);

            unsigned long long pk;
            asm("mov.b64 %0, {%1, %2};"
                : "=l"(pk) : "r"(__float_as_uint(hnew)), "r"((unsigned)(s + 1)));
            st_relaxed_u64(&g_hx[rbuf ^ 1][bg][2 * cg][0] + tid, pk);
        }
    }
}

// ---------------------------------------------------------------------------
__global__ void fc_kernel(const float* __restrict__ fc_w,
                          const float* __restrict__ fc_b,
                          float* __restrict__ out) {
    int b = blockIdx.x;
    int d = threadIdx.x;
    int bg = b >> 3, bb = b & 7;
    float acc = fc_b[d];
    #pragma unroll 8
    for (int k = 0; k < HID; k++) {
        unsigned long long v = g_hx[0][bg][k >> 3][(k & 7) * 8 + bb];
        acc += __uint_as_float((unsigned)v) * fc_w[k * DOUT + d];
    }
    out[b * DOUT + d] = acc;
}

// ---------------------------------------------------------------------------
extern "C" void kernel_launch(void* const* d_in, const int* in_sizes, int n_in,
                              void* d_out, int out_size) {
    const float* x    = (const float*)d_in[0];
    const float* W_x  = (const float*)d_in[1];
    const float* W_h  = (const float*)d_in[2];
    const float* bvec = (const float*)d_in[3];
    const float* fc_w = (const float*)d_in[4];
    const float* fc_b = (const float*)d_in[5];
    float* out = (float*)d_out;

    cudaFuncSetAttribute(xproj_kernel,
                         cudaFuncAttributeMaxDynamicSharedMemorySize, XPK_BYTES);
    cudaFuncSetAttribute(lstm_scan2,
                         cudaFuncAttributeMaxDynamicSharedMemorySize, N_SMEM_BYTES);
    cudaFuncSetAttribute(lstm_scan_fb,
                         cudaFuncAttributeMaxDynamicSharedMemorySize, F_SMEM_BYTES);

    init_kernel<<<(2 * 8 * N_NCG * 64 + 255) / 256, 256>>>();
    xproj_kernel<<<dim3(TSTEPS / 16, 8), NTHREADS, XPK_BYTES>>>(x, W_x, bvec);

    int occ = 0;
    cudaError_t e = cudaOccupancyMaxActiveBlocksPerMultiprocessor(
        &occ, lstm_scan2, NTHREADS, N_SMEM_BYTES);
    if (e == cudaSuccess && occ >= 2) {
        lstm_scan2<<<N_NCTA, NTHREADS, N_SMEM_BYTES>>>(W_h);
    } else {
        cudaGetLastError();
        lstm_scan_fb<<<F_NCTA, NTHREADS, F_SMEM_BYTES>>>(W_h);
    }

    fc_kernel<<<BATCH, DOUT>>>(fc_w, fc_b, out);
}

// round 11
// speedup vs baseline: 1.8093x; 1.8093x over previous
#include <cuda_runtime.h>
#include <cstdint>

// Problem constants
#define BATCH 64
#define TSTEPS 2048
#define DIN 128
#define HID 256
#define DOUT 128
#define G4H (4*HID)        // 1024

// Scan tiling: 16 column-groups x 8 batch-groups = 128 CTAs
#define NCTA 128
#define JPC 16             // hidden units per CTA
#define NCOL 64            // gate columns per CTA
#define BPC 8              // batches per CTA
#define KC 32              // K per warp (8 warps)
#define NTHREADS 256

// SMEM (floats)
#define SWSTR 66                         // sW2 [k][c] staging stride
#define PSTR 70                          // sPart row stride
#define SM_SW2   0                       // 256*66 = 16896 (setup only)
#define SM_H     (SM_SW2 + 256*SWSTR)    // sH [k(256)][b(8)] = 2048
#define SM_PART  (SM_H + 256*8)          // 2 x 8 x 8 x PSTR = 8960
#define SM_C     (SM_PART + 2*8*8*PSTR)  // 128
#define SM_FLOATS (SM_C + 128)
#define SMEM_BYTES (SM_FLOATS*4)         // ~113 KB

// x_proj kernel smem
#define XP_XSTRIDE 133
#define XP_WSTRIDE 132
#define XPK_SX    0
#define XPK_SW    (128*XP_XSTRIDE)
#define XPK_FLOATS (XPK_SW + 128*XP_WSTRIDE)
#define XPK_BYTES (XPK_FLOATS*4)

// Global scratch
__device__ __align__(16) float g_xp[(size_t)TSTEPS * 16 * 8 * 512];      // [t][cg][bg][bb*64+c]
// tagged h words: {hi32 = step tag, lo32 = h bits}; [buf][bg][cg][lj*8+bb]
__device__ __align__(16) unsigned long long g_hx[2][8][16][JPC*BPC];

__device__ __forceinline__ uint32_t smem_u32(const void* p) {
    return (uint32_t)__cvta_generic_to_shared(p);
}
__device__ __forceinline__ float fast_sig(float e) {   // e = expf(-x) already
    return __fdividef(1.0f, 1.0f + e);
}
__device__ __forceinline__ unsigned long long ld_relaxed_u64(
        const unsigned long long* p) {
    unsigned long long v;
    asm volatile("ld.relaxed.gpu.global.u64 %0, [%1];"
                 : "=l"(v) : "l"(p) : "memory");
    return v;
}

// ---------------------------------------------------------------------------
__global__ void init_kernel() {
    int i = blockIdx.x * blockDim.x + threadIdx.x;
    int total = 2 * 8 * 16 * JPC * BPC;
    if (i < total) ((unsigned long long*)g_hx)[i] = 0ull;  // tag 0, h = 0
}

// ---------------------------------------------------------------------------
// x_proj: g_xp[t][cg][bg][bb*64 + gate*16+lj] = x[b,t,:] . W_x[:, gcol] + bias
// ---------------------------------------------------------------------------
__global__ void __launch_bounds__(NTHREADS, 1)
xproj_kernel(const float* __restrict__ x,
             const float* __restrict__ W_x,
             const float* __restrict__ bias) {
    extern __shared__ float smem[];
    float* sX = smem + XPK_SX;
    float* sW = smem + XPK_SW;

    const int tid  = threadIdx.x;
    const int tblk = blockIdx.x;
    const int bg   = blockIdx.y;

    for (int idx = tid; idx < 128 * 32; idx += NTHREADS) {
        int r = idx >> 5, f4 = idx & 31;
        int tt = r >> 3, bb = r & 7;
        int b = bg * 8 + bb, t = tblk * 16 + tt;
        float4 v = __ldg(reinterpret_cast<const float4*>(
            x + ((size_t)b * TSTEPS + t) * DIN) + f4);
        float* dst = sX + r * XP_XSTRIDE + f4 * 4;
        dst[0] = v.x; dst[1] = v.y; dst[2] = v.z; dst[3] = v.w;
    }

    const int cq = tid & 7;
    const int rg = tid >> 3;

    for (int p = 0; p < 8; p++) {
        const int cp0 = p * 128;
        __syncthreads();
        for (int idx = tid; idx < 128 * 32; idx += NTHREADS) {
            int d = idx >> 5, c4 = idx & 31;
            float4 v = __ldg(reinterpret_cast<const float4*>(
                W_x + (size_t)d * G4H + cp0) + c4);
            float* dst = sW + d * XP_WSTRIDE + c4 * 4;
            dst[0] = v.x; dst[1] = v.y; dst[2] = v.z; dst[3] = v.w;
        }
        __syncthreads();

        unsigned long long acc[4][8];
        #pragma unroll
        for (int qq = 0; qq < 8; qq++) {
            float2 bv = __ldg(reinterpret_cast<const float2*>(
                bias + cp0 + 2 * (cq + 8 * qq)));
            unsigned long long bu;
            asm("mov.b64 %0, {%1, %2};" : "=l"(bu) : "f"(bv.x), "f"(bv.y));
            #pragma unroll
            for (int rr = 0; rr < 4; rr++) acc[rr][qq] = bu;
        }

        #pragma unroll 4
        for (int d = 0; d < 128; d++) {
            unsigned long long x2[4];
            #pragma unroll
            for (int rr = 0; rr < 4; rr++) {
                float xv = sX[(rg * 4 + rr) * XP_XSTRIDE + d];
                asm("mov.b64 %0, {%1, %1};" : "=l"(x2[rr]) : "f"(xv));
            }
            const uint32_t wrow = smem_u32(sW + d * XP_WSTRIDE + 2 * cq);
            #pragma unroll
            for (int qq = 0; qq < 8; qq++) {
                unsigned long long w2;
                asm volatile("ld.shared.u64 %0, [%1];"
                             : "=l"(w2) : "r"(wrow + qq * 64));
                #pragma unroll
                for (int rr = 0; rr < 4; rr++)
                    asm volatile("fma.rn.f32x2 %0, %1, %2, %0;"
                                 : "+l"(acc[rr][qq]) : "l"(x2[rr]), "l"(w2));
            }
        }

        #pragma unroll
        for (int rr = 0; rr < 4; rr++) {
            int r = rg * 4 + rr;
            int tt = r >> 3, bb = r & 7;
            int t = tblk * 16 + tt;
            #pragma unroll
            for (int qq = 0; qq < 8; qq++) {
                int cglob = cp0 + 2 * (cq + 8 * qq);
                int gate = cglob >> 8, rem = cglob & 255;
                int cg = rem >> 4, lj = rem & 15;
                float lo, hi;
                asm("mov.b64 {%0,%1}, %2;" : "=f"(lo), "=f"(hi) : "l"(acc[rr][qq]));
                float2* dst = reinterpret_cast<float2*>(
                    g_xp + ((size_t)((t * 16 + cg) * 8 + bg)) * 512
                         + bb * 64 + gate * 16 + lj);
                *dst = make_float2(lo, hi);
            }
        }
    }
}

// ---------------------------------------------------------------------------
// persistent LSTM scan: W_h in registers; self-tagging h words;
// two-phase poll; producer/consumer warp split at the barrier.
// ---------------------------------------------------------------------------
__global__ void __launch_bounds__(NTHREADS, 1)
lstm_scan_kernel(const float* __restrict__ W_h) {
    extern __shared__ float smem[];
    float* sW2   = smem + SM_SW2;   // [k][c] staging (setup only)
    float* sH    = smem + SM_H;     // [k(256)][b(8)]
    float* sPart = smem + SM_PART;  // [buf][w][b][c] stride PSTR
    float* sC    = smem + SM_C;     // [lj*8+bb]

    const int tid = threadIdx.x;
    const int cg  = blockIdx.x & 15;
    const int bg  = blockIdx.x >> 4;
    const int j0  = cg * JPC;

    // ---- stage W_h slice as [k][c] then load into registers
    for (int idx = tid; idx < KC * 8 * NCOL; idx += NTHREADS) {
        int k = idx >> 6, c = idx & 63;
        int gate = c >> 4, lj = c & 15;
        sW2[k * SWSTR + c] = W_h[(size_t)k * G4H + gate * HID + j0 + lj];
    }
    if (tid < JPC * BPC) sC[tid] = 0.0f;
    __syncthreads();

    const int w    = tid >> 5;            // warp = k-chunk
    const int lane = tid & 31;
    const int hw   = lane >> 4;           // batch half
    const int lc   = lane & 15;           // owns cols 4lc..4lc+3
    const int k0   = w * KC;
    const int c0   = 4 * lc;

    unsigned long long wreg[2][KC];       // [pair][k]
    {
        const uint32_t wb = smem_u32(sW2 + k0 * SWSTR + c0);
        #pragma unroll
        for (int k = 0; k < KC; k++) {
            asm volatile("ld.shared.u64 %0, [%1];"
                         : "=l"(wreg[0][k]) : "r"(wb + k * (SWSTR * 4)));
            asm volatile("ld.shared.u64 %0, [%1];"
                         : "=l"(wreg[1][k]) : "r"(wb + k * (SWSTR * 4) + 8));
        }
    }
    __syncthreads();   // sW2 dead after this

    const uint32_t hbase  = smem_u32(sH + k0 * BPC + 4 * hw);
    const uint32_t hstore = smem_u32(sH + k0 * BPC) + lane * 16;

    const int lj = tid >> 3;              // epilogue decode (tid<128)
    const int bb = tid & 7;

    for (int s = 0; s < TSTEPS; s++) {
        const int rbuf = s & 1;
        float* sP = sPart + rbuf * (8 * BPC * PSTR);

        // ---- prefetch x_proj gate inputs for epilogue (tid<128)
        float xr[4];
        if (tid < JPC * BPC) {
            const float* xpb = g_xp + ((size_t)((s * 16 + cg) * 8 + bg)) * 512
                             + bb * 64 + lj;
            #pragma unroll
            for (int gate = 0; gate < 4; gate++)
                xr[gate] = __ldg(xpb + gate * 16);
        }

        // ---- two-phase poll on tagged producer words
        const unsigned long long* pA = &g_hx[rbuf][bg][2 * w][4 * lane];
        const unsigned long long* pB = &g_hx[rbuf][bg][2 * w + 1][4 * lane];
        unsigned long long va[4], vb[4];
        const unsigned exp_tag = (unsigned)s;

        // phase 1: spin on one sentinel word per producer block (2 loads/lane)
        for (;;) {
            va[3] = ld_relaxed_u64(pA + 3);
            vb[3] = ld_relaxed_u64(pB + 3);
            bool ok = ((unsigned)(va[3] >> 32) == exp_tag) &&
                      ((unsigned)(vb[3] >> 32) == exp_tag);
            if (__all_sync(0xffffffffu, ok)) break;
        }
        // phase 2: bulk-read the rest; re-verify stale words (rare)
        #pragma unroll
        for (int i = 0; i < 3; i++) { va[i] = ld_relaxed_u64(pA + i);
                                      vb[i] = ld_relaxed_u64(pB + i); }
        for (;;) {
            bool all_ok = true;
            #pragma unroll
            for (int i = 0; i < 3; i++) {
                if ((unsigned)(va[i] >> 32) != exp_tag) {
                    va[i] = ld_relaxed_u64(pA + i); all_ok = false;
                }
                if ((unsigned)(vb[i] >> 32) != exp_tag) {
                    vb[i] = ld_relaxed_u64(pB + i); all_ok = false;
                }
            }
            if (__all_sync(0xffffffffu, all_ok)) break;
        }

        // ---- unpack h and stage into my private sH rows
        asm volatile("st.shared.v4.f32 [%0], {%1,%2,%3,%4};"
                     :: "r"(hstore),
                        "f"(__uint_as_float((unsigned)va[0])),
                        "f"(__uint_as_float((unsigned)va[1])),
                        "f"(__uint_as_float((unsigned)va[2])),
                        "f"(__uint_as_float((unsigned)va[3])));
        asm volatile("st.shared.v4.f32 [%0], {%1,%2,%3,%4};"
                     :: "r"(hstore + 512),
                        "f"(__uint_as_float((unsigned)vb[0])),
                        "f"(__uint_as_float((unsigned)vb[1])),
                        "f"(__uint_as_float((unsigned)vb[2])),
                        "f"(__uint_as_float((unsigned)vb[3])));
        __syncwarp();

        // ---- GEMM: per k: 1 broadcast LDS.128 + 4 splats + 8 FMA2
        unsigned long long acc[2][4];
        #pragma unroll
        for (int p = 0; p < 2; p++)
            #pragma unroll
            for (int i = 0; i < 4; i++) acc[p][i] = 0ull;

        #pragma unroll
        for (int k = 0; k < KC; k++) {
            float h0, h1, h2f, h3;
            asm volatile("ld.shared.v4.f32 {%0,%1,%2,%3}, [%4];"
                         : "=f"(h0), "=f"(h1), "=f"(h2f), "=f"(h3)
                         : "r"(hbase + k * 32));
            unsigned long long hh[4];
            asm("mov.b64 %0, {%1, %1};" : "=l"(hh[0]) : "f"(h0));
            asm("mov.b64 %0, {%1, %1};" : "=l"(hh[1]) : "f"(h1));
            asm("mov.b64 %0, {%1, %1};" : "=l"(hh[2]) : "f"(h2f));
            asm("mov.b64 %0, {%1, %1};" : "=l"(hh[3]) : "f"(h3));
            #pragma unroll
            for (int i = 0; i < 4; i++) {
                asm volatile("fma.rn.f32x2 %0, %1, %2, %0;"
                             : "+l"(acc[0][i]) : "l"(hh[i]), "l"(wreg[0][k]));
                asm volatile("fma.rn.f32x2 %0, %1, %2, %0;"
                             : "+l"(acc[1][i]) : "l"(hh[i]), "l"(wreg[1][k]));
            }
        }

        // ---- write partials
        #pragma unroll
        for (int i = 0; i < 4; i++) {
            int row = (w * BPC + 4 * hw + i) * PSTR;
            *reinterpret_cast<unsigned long long*>(sP + row + c0)     = acc[0][i];
            *reinterpret_cast<unsigned long long*>(sP + row + c0 + 2) = acc[1][i];
        }

        // ---- barrier split: producers (warps 0-3) sync; helpers arrive & go
        if (tid < JPC * BPC) {
            if ((s & 1) == 0)
                asm volatile("bar.sync 1, 256;" ::: "memory");
            else
                asm volatile("bar.sync 2, 256;" ::: "memory");

            // epilogue: reduce 8 partials, activations, tagged publish
            float g4[4];
            #pragma unroll
            for (int gate = 0; gate < 4; gate++) {
                int c = gate * JPC + lj;
                float v = xr[gate];
                #pragma unroll
                for (int q = 0; q < 8; q++)
                    v += sP[(q * BPC + bb) * PSTR + c];
                g4[gate] = v;
            }
            // pipeline the 4 MUFU exps before the divides
            float e0 = __expf(-g4[0]);
            float e1 = __expf(-g4[1]);
            float e2 = __expf(-2.0f * g4[2]);
            float e3 = __expf(-g4[3]);
            float ig = fast_sig(e0);
            float fg = fast_sig(e1);
            float gg = __fdividef(2.0f, 1.0f + e2) - 1.0f;
            float og = fast_sig(e3);
            float cnew = fg * sC[tid] + ig * gg;
            sC[tid] = cnew;
            float ech = __expf(-2.0f * cnew);
            float hnew = og * (__fdividef(2.0f, 1.0f + ech) - 1.0f);

            unsigned long long pk;
            asm("mov.b64 %0, {%1, %2};"
                : "=l"(pk) : "r"(__float_as_uint(hnew)), "r"((unsigned)(s + 1)));
            asm volatile("st.relaxed.gpu.global.u64 [%0], %1;"
                         :: "l"(&g_hx[rbuf ^ 1][bg][cg][tid]), "l"(pk)
                         : "memory");
        } else {
            if ((s & 1) == 0)
                asm volatile("bar.arrive 1, 256;" ::: "memory");
            else
                asm volatile("bar.arrive 2, 256;" ::: "memory");
            // helpers run ahead into step s+1 (sH rows warp-private,
            // sPart double-buffered, data deps bound skew to < 2 steps)
        }
    }
}

// ---------------------------------------------------------------------------
// final FC: out[b][d] = sum_k h_final[k][b] * fc_w[k][d] + fc_b[d]
// h_2048 (tag 2048) lives in g_hx[0][bg][k>>4][(k&15)*8+bb] low bits
// ---------------------------------------------------------------------------
__global__ void fc_kernel(const float* __restrict__ fc_w,
                          const float* __restrict__ fc_b,
                          float* __restrict__ out) {
    int b = blockIdx.x;
    int d = threadIdx.x;
    int bg = b >> 3, bb = b & 7;
    float acc = fc_b[d];
    #pragma unroll 8
    for (int k = 0; k < HID; k++) {
        unsigned long long v = g_hx[0][bg][k >> 4][(k & 15) * 8 + bb];
        acc += __uint_as_float((unsigned)v) * fc_w[k * DOUT + d];
    }
    out[b * DOUT + d] = acc;
}

// ---------------------------------------------------------------------------
extern "C" void kernel_launch(void* const* d_in, const int* in_sizes, int n_in,
                              void* d_out, int out_size) {
    const float* x    = (const float*)d_in[0];
    const float* W_x  = (const float*)d_in[1];
    const float* W_h  = (const float*)d_in[2];
    const float* bvec = (const float*)d_in[3];
    const float* fc_w = (const float*)d_in[4];
    const float* fc_b = (const float*)d_in[5];
    float* out = (float*)d_out;

    cudaFuncSetAttribute(xproj_kernel,
                         cudaFuncAttributeMaxDynamicSharedMemorySize, XPK_BYTES);
    cudaFuncSetAttribute(lstm_scan_kernel,
                         cudaFuncAttributeMaxDynamicSharedMemorySize, SMEM_BYTES);

    init_kernel<<<(2 * 8 * 16 * JPC * BPC + 255) / 256, 256>>>();
    xproj_kernel<<<dim3(TSTEPS / 16, 8), NTHREADS, XPK_BYTES>>>(x, W_x, bvec);
    lstm_scan_kernel<<<NCTA, NTHREADS, SMEM_BYTES>>>(W_h);
    fc_kernel<<<BATCH, DOUT>>>(fc_w, fc_b, out);
}

// round 12
// speedup vs baseline: 1.8174x; 1.0045x over previous
#include <cuda_runtime.h>
#include <cstdint>

// Problem constants
#define BATCH 64
#define TSTEPS 2048
#define DIN 128
#define HID 256
#define DOUT 128
#define G4H (4*HID)        // 1024

// Scan tiling: 16 column-groups x 8 batch-groups = 128 CTAs (bids 0-127)
#define NCTA_SCAN 128
#define JPC 16             // hidden units per CTA
#define NCOL 64            // gate columns per CTA
#define BPC 8              // batches per CTA
#define KC 32              // K per warp (8 warps)
#define NTHREADS 256

// xproj: 128 tblocks x 8 bg = 1024 CTAs (bids 128-1151)
#define NCTA_XP 1024
#define NCTA_TOTAL (NCTA_SCAN + NCTA_XP)

// scan SMEM layout (floats) — small so it fits under the xproj request
#define PSTR 70
#define S_H     0                        // sH [k(256)][b(8)] = 2048
#define S_PART  (S_H + 256*8)            // 2 x 8 x 8 x PSTR = 8960
#define S_C     (S_PART + 2*8*8*PSTR)    // 128

// xproj SMEM layout (floats)
#define XP_XSTRIDE 133
#define XP_WSTRIDE 132
#define XPK_SX    0
#define XPK_SW    (128*XP_XSTRIDE)
#define XPK_FLOATS (XPK_SW + 128*XP_WSTRIDE)
#define XPK_BYTES (XPK_FLOATS*4)         // ~136 KB (the fused kernel's request)

// Global scratch
__device__ __align__(16) float g_xp[(size_t)TSTEPS * 16 * 8 * 512];   // [t][cg][bg][bb*64+c]
// tagged h words {hi32=tag, lo32=h bits}: [buf][bg][cg][lj*8+bb]
__device__ __align__(16) unsigned long long g_hx[2][8][16][JPC*BPC];
__device__ unsigned xp_cnt[128 * 32];                                  // per tblk, 128B apart

__device__ __forceinline__ uint32_t smem_u32(const void* p) {
    return (uint32_t)__cvta_generic_to_shared(p);
}
__device__ __forceinline__ float fast_sig(float e) {   // e = expf(-x)
    return __fdividef(1.0f, 1.0f + e);
}
__device__ __forceinline__ unsigned long long ld_relaxed_u64(
        const unsigned long long* p) {
    unsigned long long v;
    asm volatile("ld.relaxed.gpu.global.u64 %0, [%1];"
                 : "=l"(v) : "l"(p) : "memory");
    return v;
}

// ---------------------------------------------------------------------------
__global__ void init_kernel() {
    int i = blockIdx.x * blockDim.x + threadIdx.x;
    int total = 2 * 8 * 16 * JPC * BPC;            // 32768 words
    if (i < total) ((unsigned long long*)g_hx)[i] = 0ull;
    if (i < 128 * 32) xp_cnt[i] = 0u;
}

// ===========================================================================
// xproj body: g_xp[t][cg][bg][bb*64 + gate*16+lj] = x[b,t,:].W_x[:,gcol]+bias
// ===========================================================================
__device__ void xproj_body(const float* __restrict__ x,
                           const float* __restrict__ W_x,
                           const float* __restrict__ bias,
                           int idx) {
    extern __shared__ float smem[];
    float* sX = smem + XPK_SX;
    float* sW = smem + XPK_SW;

    const int tid  = threadIdx.x;
    const int tblk = idx >> 3;
    const int bg   = idx & 7;

    for (int i = tid; i < 128 * 32; i += NTHREADS) {
        int r = i >> 5, f4 = i & 31;
        int tt = r >> 3, bb = r & 7;
        int b = bg * 8 + bb, t = tblk * 16 + tt;
        float4 v = __ldg(reinterpret_cast<const float4*>(
            x + ((size_t)b * TSTEPS + t) * DIN) + f4);
        float* dst = sX + r * XP_XSTRIDE + f4 * 4;
        dst[0] = v.x; dst[1] = v.y; dst[2] = v.z; dst[3] = v.w;
    }

    const int cq = tid & 7;
    const int rg = tid >> 3;

    for (int p = 0; p < 8; p++) {
        const int cp0 = p * 128;
        __syncthreads();
        for (int i = tid; i < 128 * 32; i += NTHREADS) {
            int d = i >> 5, c4 = i & 31;
            float4 v = __ldg(reinterpret_cast<const float4*>(
                W_x + (size_t)d * G4H + cp0) + c4);
            float* dst = sW + d * XP_WSTRIDE + c4 * 4;
            dst[0] = v.x; dst[1] = v.y; dst[2] = v.z; dst[3] = v.w;
        }
        __syncthreads();

        unsigned long long acc[4][8];
        #pragma unroll
        for (int qq = 0; qq < 8; qq++) {
            float2 bv = __ldg(reinterpret_cast<const float2*>(
                bias + cp0 + 2 * (cq + 8 * qq)));
            unsigned long long bu;
            asm("mov.b64 %0, {%1, %2};" : "=l"(bu) : "f"(bv.x), "f"(bv.y));
            #pragma unroll
            for (int rr = 0; rr < 4; rr++) acc[rr][qq] = bu;
        }

        #pragma unroll 4
        for (int d = 0; d < 128; d++) {
            unsigned long long x2[4];
            #pragma unroll
            for (int rr = 0; rr < 4; rr++) {
                float xv = sX[(rg * 4 + rr) * XP_XSTRIDE + d];
                asm("mov.b64 %0, {%1, %1};" : "=l"(x2[rr]) : "f"(xv));
            }
            const uint32_t wrow = smem_u32(sW + d * XP_WSTRIDE + 2 * cq);
            #pragma unroll
            for (int qq = 0; qq < 8; qq++) {
                unsigned long long w2;
                asm volatile("ld.shared.u64 %0, [%1];"
                             : "=l"(w2) : "r"(wrow + qq * 64));
                #pragma unroll
                for (int rr = 0; rr < 4; rr++)
                    asm volatile("fma.rn.f32x2 %0, %1, %2, %0;"
                                 : "+l"(acc[rr][qq]) : "l"(x2[rr]), "l"(w2));
            }
        }

        #pragma unroll
        for (int rr = 0; rr < 4; rr++) {
            int r = rg * 4 + rr;
            int tt = r >> 3, bb = r & 7;
            int t = tblk * 16 + tt;
            #pragma unroll
            for (int qq = 0; qq < 8; qq++) {
                int cglob = cp0 + 2 * (cq + 8 * qq);
                int gate = cglob >> 8, rem = cglob & 255;
                int cg = rem >> 4, lj = rem & 15;
                float lo, hi;
                asm("mov.b64 {%0,%1}, %2;" : "=f"(lo), "=f"(hi) : "l"(acc[rr][qq]));
                float2* dst = reinterpret_cast<float2*>(
                    g_xp + ((size_t)((t * 16 + cg) * 8 + bg)) * 512
                         + bb * 64 + gate * 16 + lj);
                *dst = make_float2(lo, hi);
            }
        }
    }

    // publish tblk progress (release pairs with scan's acquire)
    __syncthreads();
    if (tid == 0)
        asm volatile("red.release.gpu.global.add.u32 [%0], %1;"
                     :: "l"(&xp_cnt[tblk * 32]), "r"(1u) : "memory");
}

// ===========================================================================
// scan body: W_h in regs (direct from global); self-tagging h words;
// R9 bulk poll; producer/consumer warp split at the barrier.
// ===========================================================================
__device__ void scan_body(const float* __restrict__ W_h) {
    extern __shared__ float smem[];
    float* sH    = smem + S_H;      // [k(256)][b(8)]
    float* sPart = smem + S_PART;   // [buf][w][b][c] stride PSTR
    float* sC    = smem + S_C;      // [lj*8+bb]

    const int tid = threadIdx.x;
    const int cg  = blockIdx.x & 15;
    const int bg  = blockIdx.x >> 4;
    const int j0  = cg * JPC;

    const int w    = tid >> 5;            // warp = k-chunk
    const int lane = tid & 31;
    const int hw   = lane >> 4;           // batch half
    const int lc   = lane & 15;           // owns cols 4lc..4lc+3
    const int k0   = w * KC;
    const int c0   = 4 * lc;

    // ---- W_h slice straight from global into registers (setup only)
    // cols c0..c0+3 are consecutive within one gate (c0 % 4 == 0, lj <= 12)
    unsigned long long wreg[2][KC];       // [pair][k]
    {
        const int gate = c0 >> 4;
        const int ljw  = c0 & 15;
        const float* wp = W_h + (size_t)k0 * G4H + gate * HID + j0 + ljw;
        #pragma unroll
        for (int k = 0; k < KC; k++) {
            float4 wv = __ldg(reinterpret_cast<const float4*>(
                wp + (size_t)k * G4H));
            asm("mov.b64 %0, {%1, %2};" : "=l"(wreg[0][k]) : "f"(wv.x), "f"(wv.y));
            asm("mov.b64 %0, {%1, %2};" : "=l"(wreg[1][k]) : "f"(wv.z), "f"(wv.w));
        }
    }
    if (tid < JPC * BPC) sC[tid] = 0.0f;
    __syncthreads();

    const uint32_t hbase  = smem_u32(sH + k0 * BPC + 4 * hw);
    const uint32_t hstore = smem_u32(sH + k0 * BPC) + lane * 16;

    const int lj = tid >> 3;              // epilogue decode (tid<128)
    const int bb = tid & 7;

    for (int s = 0; s < TSTEPS; s++) {
        const int rbuf = s & 1;
        float* sP = sPart + rbuf * (8 * BPC * PSTR);

        // ---- gate on xproj progress (once per 16 steps; epi warps only)
        if ((s & 15) == 0 && tid < JPC * BPC) {
            if ((tid & 31) == 0) {
                const unsigned* cp = &xp_cnt[(s >> 4) * 32];
                unsigned v;
                for (;;) {
                    asm volatile("ld.acquire.gpu.global.u32 %0, [%1];"
                                 : "=r"(v) : "l"(cp) : "memory");
                    if (v >= 8u) break;
                    __nanosleep(128);
                }
            }
            __syncwarp();
        }

        // ---- prefetch x_proj gate inputs for epilogue (tid<128)
        float xr[4];
        if (tid < JPC * BPC) {
            const float* xpb = g_xp + ((size_t)((s * 16 + cg) * 8 + bg)) * 512
                             + bb * 64 + lj;
            #pragma unroll
            for (int gate = 0; gate < 4; gate++)
                xr[gate] = __ldcg(xpb + gate * 16);
        }

        // ---- R9 bulk poll on tagged producer words (data in hand at detect)
        const unsigned long long* pA = &g_hx[rbuf][bg][2 * w][4 * lane];
        const unsigned long long* pB = &g_hx[rbuf][bg][2 * w + 1][4 * lane];
        unsigned long long va[4], vb[4];
        const unsigned exp_tag = (unsigned)s;
        #pragma unroll
        for (int i = 0; i < 4; i++) { va[i] = ld_relaxed_u64(pA + i);
                                      vb[i] = ld_relaxed_u64(pB + i); }
        for (;;) {
            bool all_ok = true;
            #pragma unroll
            for (int i = 0; i < 4; i++) {
                if ((unsigned)(va[i] >> 32) != exp_tag) {
                    va[i] = ld_relaxed_u64(pA + i); all_ok = false;
                }
                if ((unsigned)(vb[i] >> 32) != exp_tag) {
                    vb[i] = ld_relaxed_u64(pB + i); all_ok = false;
                }
            }
            if (__all_sync(0xffffffffu, all_ok)) break;
        }

        // ---- unpack h and stage into my private sH rows
        asm volatile("st.shared.v4.f32 [%0], {%1,%2,%3,%4};"
                     :: "r"(hstore),
                        "f"(__uint_as_float((unsigned)va[0])),
                        "f"(__uint_as_float((unsigned)va[1])),
                        "f"(__uint_as_float((unsigned)va[2])),
                        "f"(__uint_as_float((unsigned)va[3])));
        asm volatile("st.shared.v4.f32 [%0], {%1,%2,%3,%4};"
                     :: "r"(hstore + 512),
                        "f"(__uint_as_float((unsigned)vb[0])),
                        "f"(__uint_as_float((unsigned)vb[1])),
                        "f"(__uint_as_float((unsigned)vb[2])),
                        "f"(__uint_as_float((unsigned)vb[3])));
        __syncwarp();

        // ---- GEMM: per k: 1 broadcast LDS.128 + 4 splats + 8 FMA2
        unsigned long long acc[2][4];
        #pragma unroll
        for (int p = 0; p < 2; p++)
            #pragma unroll
            for (int i = 0; i < 4; i++) acc[p][i] = 0ull;

        #pragma unroll
        for (int k = 0; k < KC; k++) {
            float h0, h1, h2f, h3;
            asm volatile("ld.shared.v4.f32 {%0,%1,%2,%3}, [%4];"
                         : "=f"(h0), "=f"(h1), "=f"(h2f), "=f"(h3)
                         : "r"(hbase + k * 32));
            unsigned long long hh[4];
            asm("mov.b64 %0, {%1, %1};" : "=l"(hh[0]) : "f"(h0));
            asm("mov.b64 %0, {%1, %1};" : "=l"(hh[1]) : "f"(h1));
            asm("mov.b64 %0, {%1, %1};" : "=l"(hh[2]) : "f"(h2f));
            asm("mov.b64 %0, {%1, %1};" : "=l"(hh[3]) : "f"(h3));
            #pragma unroll
            for (int i = 0; i < 4; i++) {
                asm volatile("fma.rn.f32x2 %0, %1, %2, %0;"
                             : "+l"(acc[0][i]) : "l"(hh[i]), "l"(wreg[0][k]));
                asm volatile("fma.rn.f32x2 %0, %1, %2, %0;"
                             : "+l"(acc[1][i]) : "l"(hh[i]), "l"(wreg[1][k]));
            }
        }

        // ---- write partials
        #pragma unroll
        for (int i = 0; i < 4; i++) {
            int row = (w * BPC + 4 * hw + i) * PSTR;
            *reinterpret_cast<unsigned long long*>(sP + row + c0)     = acc[0][i];
            *reinterpret_cast<unsigned long long*>(sP + row + c0 + 2) = acc[1][i];
        }

        // ---- barrier split: epi warps sync; helper warps arrive & run ahead
        if (tid < JPC * BPC) {
            if ((s & 1) == 0)
                asm volatile("bar.sync 1, 256;" ::: "memory");
            else
                asm volatile("bar.sync 2, 256;" ::: "memory");

            float g4[4];
            #pragma unroll
            for (int gate = 0; gate < 4; gate++) {
                int c = gate * JPC + lj;
                float v = xr[gate];
                #pragma unroll
                for (int q = 0; q < 8; q++)
                    v += sP[(q * BPC + bb) * PSTR + c];
                g4[gate] = v;
            }
            float e0 = __expf(-g4[0]);
            float e1 = __expf(-g4[1]);
            float e2 = __expf(-2.0f * g4[2]);
            float e3 = __expf(-g4[3]);
            float ig = fast_sig(e0);
            float fg = fast_sig(e1);
            float gg = __fdividef(2.0f, 1.0f + e2) - 1.0f;
            float og = fast_sig(e3);
            float cnew = fg * sC[tid] + ig * gg;
            sC[tid] = cnew;
            float ech = __expf(-2.0f * cnew);
            float hnew = og * (__fdividef(2.0f, 1.0f + ech) - 1.0f);

            unsigned long long pk;
            asm("mov.b64 %0, {%1, %2};"
                : "=l"(pk) : "r"(__float_as_uint(hnew)), "r"((unsigned)(s + 1)));
            asm volatile("st.relaxed.gpu.global.u64 [%0], %1;"
                         :: "l"(&g_hx[rbuf ^ 1][bg][cg][tid]), "l"(pk)
                         : "memory");
        } else {
            if ((s & 1) == 0)
                asm volatile("bar.arrive 1, 256;" ::: "memory");
            else
                asm volatile("bar.arrive 2, 256;" ::: "memory");
            // helpers run ahead into step s+1 (sH rows warp-private,
            // sPart double-buffered; data deps bound skew to < 2 steps)
        }
    }
}

// ===========================================================================
// fused kernel: bids 0-127 = persistent scan (wave-1), 128-1151 = xproj tiles
// ===========================================================================
__global__ void __launch_bounds__(NTHREADS, 1)
fused_kernel(const float* __restrict__ x,
             const float* __restrict__ W_x,
             const float* __restrict__ W_h,
             const float* __restrict__ bias) {
    if (blockIdx.x < NCTA_SCAN)
        scan_body(W_h);
    else
        xproj_body(x, W_x, bias, blockIdx.x - NCTA_SCAN);
}

// ---------------------------------------------------------------------------
// final FC: out[b][d] = sum_k h_final[k][b] * fc_w[k][d] + fc_b[d]
// h_2048 (tag 2048) lives in g_hx[0][bg][k>>4][(k&15)*8+bb] low bits
// ---------------------------------------------------------------------------
__global__ void fc_kernel(const float* __restrict__ fc_w,
                          const float* __restrict__ fc_b,
                          float* __restrict__ out) {
    int b = blockIdx.x;
    int d = threadIdx.x;
    int bg = b >> 3, bb = b & 7;
    float acc = fc_b[d];
    #pragma unroll 8
    for (int k = 0; k < HID; k++) {
        unsigned long long v = g_hx[0][bg][k >> 4][(k & 15) * 8 + bb];
        acc += __uint_as_float((unsigned)v) * fc_w[k * DOUT + d];
    }
    out[b * DOUT + d] = acc;
}

// ---------------------------------------------------------------------------
extern "C" void kernel_launch(void* const* d_in, const int* in_sizes, int n_in,
                              void* d_out, int out_size) {
    const float* x    = (const float*)d_in[0];
    const float* W_x  = (const float*)d_in[1];
    const float* W_h  = (const float*)d_in[2];
    const float* bvec = (const float*)d_in[3];
    const float* fc_w = (const float*)d_in[4];
    const float* fc_b = (const float*)d_in[5];
    float* out = (float*)d_out;

    cudaFuncSetAttribute(fused_kernel,
                         cudaFuncAttributeMaxDynamicSharedMemorySize, XPK_BYTES);

    init_kernel<<<(2 * 8 * 16 * JPC * BPC + 255) / 256, 256>>>();
    fused_kernel<<<NCTA_TOTAL, NTHREADS, XPK_BYTES>>>(x, W_x, W_h, bvec);
    fc_kernel<<<BATCH, DOUT>>>(fc_w, fc_b, out);
}